// round 15
// baseline (speedup 1.0000x reference)
#include <cuda_runtime.h>
#include <cstdint>
#include <cstddef>

#define MD   28
#define D    784
#define SEQ  128
#define NB   512          // batches
#define NT   3            // tasks (warps) per batch; task = 2 chains
#define MAT_BYTES 3136
#define SMEM_BYTES (4 * MAT_BYTES + 16)     // A0,A1,[pad],B0,B1 for ONE warp

// fan-in scratch (no cudaMalloc allowed)
__device__ __align__(16) float g_q[(size_t)NB * NT * D];
__device__ int g_cnt[NB];

// ---------- packed f32x2 helpers ----------
__device__ __forceinline__ unsigned long long pack2(float lo, float hi) {
    unsigned long long r;
    asm("mov.b64 %0, {%1, %2};" : "=l"(r) : "f"(lo), "f"(hi));
    return r;
}
__device__ __forceinline__ void unpack2(unsigned long long v, float& lo, float& hi) {
    asm("mov.b64 {%0, %1}, %2;" : "=f"(lo), "=f"(hi) : "l"(v));
}
__device__ __forceinline__ unsigned long long mul2(unsigned long long a, unsigned long long b) {
    unsigned long long r;
    asm("mul.rn.f32x2 %0, %1, %2;" : "=l"(r) : "l"(a), "l"(b));
    return r;
}
__device__ __forceinline__ void fma2(unsigned long long& d, unsigned long long a, unsigned long long b) {
    asm("fma.rn.f32x2 %0, %1, %2, %0;" : "+l"(d) : "l"(a), "l"(b));
}

// ---------- TMA bulk-copy + mbarrier helpers ----------
__device__ __forceinline__ unsigned s2u(const void* p) {
    return (unsigned)__cvta_generic_to_shared(p);
}
__device__ __forceinline__ void mbar_init(void* mbar) {
    asm volatile("mbarrier.init.shared.b64 [%0], %1;"
                 :: "r"(s2u(mbar)), "r"(1u) : "memory");
}
__device__ __forceinline__ void mbar_expect_tx(void* mbar, unsigned bytes) {
    asm volatile("mbarrier.arrive.expect_tx.shared.b64 _, [%0], %1;"
                 :: "r"(s2u(mbar)), "r"(bytes) : "memory");
}
__device__ __forceinline__ void mbar_wait(void* mbar, unsigned parity) {
    asm volatile(
        "{\n\t"
        ".reg .pred P;\n"
        "W%=:\n\t"
        "mbarrier.try_wait.parity.acquire.cta.shared::cta.b64 P, [%0], %1, 0x989680;\n\t"
        "@P bra D%=;\n\t"
        "bra W%=;\n"
        "D%=:\n\t"
        "}"
        :: "r"(s2u(mbar)), "r"(parity) : "memory");
}
__device__ __forceinline__ void bulk_cp(void* dst_smem, const void* src_gmem,
                                        unsigned bytes, void* mbar) {
    asm volatile(
        "cp.async.bulk.shared::cta.global.mbarrier::complete_tx::bytes [%0], [%1], %2, [%3];"
        :: "r"(s2u(dst_smem)), "l"(src_gmem), "r"(bytes), "r"(s2u(mbar)) : "memory");
}
__device__ __forceinline__ void fence_proxy_async_cta() {
    asm volatile("fence.proxy.async.shared::cta;" ::: "memory");
}

// Two rows per lane: {c0,c1} = rows sl, sl+14. W in smem; the two 16-lane
// halves may pass different pointers (dual broadcast, 1-2 wavefronts).
__device__ __forceinline__ void mm_step2(float c0[MD], float c1[MD],
                                         const float4* __restrict__ w) {
    unsigned long long a0[14], a1[14];
    #pragma unroll
    for (int k = 0; k < MD; ++k) {
        unsigned long long k0 = pack2(c0[k], c0[k]);
        unsigned long long k1 = pack2(c1[k], c1[k]);
        #pragma unroll
        for (int q = 0; q < 7; ++q) {
            float4 wv = w[k * 7 + q];
            unsigned long long wlo = pack2(wv.x, wv.y);
            unsigned long long whi = pack2(wv.z, wv.w);
            if (k == 0) {
                a0[2*q]   = mul2(k0, wlo);
                a0[2*q+1] = mul2(k0, whi);
                a1[2*q]   = mul2(k1, wlo);
                a1[2*q+1] = mul2(k1, whi);
            } else {
                fma2(a0[2*q],   k0, wlo);
                fma2(a0[2*q+1], k0, whi);
                fma2(a1[2*q],   k1, wlo);
                fma2(a1[2*q+1], k1, whi);
            }
        }
    }
    #pragma unroll
    for (int q = 0; q < 14; ++q) {
        unpack2(a0[q], c0[2*q], c0[2*q+1]);
        unpack2(a1[q], c1[2*q], c1[2*q+1]);
    }
}

__device__ __forceinline__ void store2(float* tile, int r0, int r1,
                                       const float c0[MD], const float c1[MD]) {
    float4* p0 = (float4*)(tile + r0 * MD);
    float4* p1 = (float4*)(tile + r1 * MD);
    #pragma unroll
    for (int q = 0; q < 7; ++q) {
        p0[q] = make_float4(c0[4*q], c0[4*q+1], c0[4*q+2], c0[4*q+3]);
        p1[q] = make_float4(c1[4*q], c1[4*q+1], c1[4*q+2], c1[4*q+3]);
    }
}

// zero the fan-in counters (prologue launch, graph-capturable)
__global__ void w2m_zero(void) { g_cnt[threadIdx.x] = 0; }

// One block = one WARP = one task: chains {A,B} of batch b, task t:
//   t0: [0,22)+[22,44)   t1: [44,65)+[65,86)   t2: [86,107)+[107,128)
// Publishes Q_t = P_A*P_B to scratch; last finisher folds out = Q0*Q1*Q2.
__global__ void __launch_bounds__(32, 12)
w2m_main(const int* __restrict__ sent, const float* __restrict__ tab,
         float* __restrict__ out)
{
    __shared__ __align__(16) char wbase[SMEM_BYTES];
    __shared__ __align__(8) unsigned long long mbar[2];

    int bid  = blockIdx.x;
    int b    = bid / NT;
    int t    = bid % NT;
    int lane = (int)threadIdx.x;
    int h    = lane >> 4;
    int sl   = lane & 15;
    int act  = (sl < 14);
    int r0   = act ? sl : 0;
    int r1   = act ? sl + 14 : 0;

    int clen   = (t == 0) ? 22 : 21;
    int startA = (t == 0) ? 0 : ((t == 1) ? 44 : 86);
    int startB = startA + clen;

    float4* bufA0 = (float4*)(wbase);
    float4* bufA1 = (float4*)(wbase + MAT_BYTES);
    float4* bufB0 = (float4*)(wbase + 2 * MAT_BYTES + 16);
    float4* bufB1 = (float4*)(wbase + 3 * MAT_BYTES + 16);

    if (lane == 0) {
        mbar_init(&mbar[0]);
        mbar_init(&mbar[1]);
        fence_proxy_async_cta();
    }
    __syncwarp();

    int la = (lane < clen) ? lane : 0;
    int iA = sent[b * SEQ + startA + la];
    int iB = sent[b * SEQ + startB + la];

    // TMA for step 1 of both chains into stage 1
    {
        int a1i = __shfl_sync(0xffffffffu, iA, 1);
        int b1i = __shfl_sync(0xffffffffu, iB, 1);
        if (lane == 0) {
            mbar_expect_tx(&mbar[1], 2 * MAT_BYTES);
            bulk_cp(bufA1, tab + (size_t)a1i * D, MAT_BYTES, &mbar[1]);
            bulk_cp(bufB1, tab + (size_t)b1i * D, MAT_BYTES, &mbar[1]);
        }
    }

    // c = rows r0,r1 of matrix 0 of this half's chain
    float c0[MD], c1[MD];
    {
        int a0i = __shfl_sync(0xffffffffu, iA, 0);
        int b0i = __shfl_sync(0xffffffffu, iB, 0);
        int i0  = h ? b0i : a0i;
        const float4* w0 = (const float4*)(tab + (size_t)i0 * D);
        #pragma unroll
        for (int q = 0; q < 7; ++q) {
            float4 v0 = __ldg(w0 + r0 * 7 + q);
            float4 v1 = __ldg(w0 + r1 * 7 + q);
            c0[4*q] = v0.x; c0[4*q+1] = v0.y; c0[4*q+2] = v0.z; c0[4*q+3] = v0.w;
            c1[4*q] = v1.x; c1[4*q+1] = v1.y; c1[4*q+2] = v1.z; c1[4*q+3] = v1.w;
        }
    }

    unsigned ph0 = 0, ph1 = 0;

    #pragma unroll 1
    for (int s = 1; s < clen; ++s) {
        if (s + 1 < clen) {
            int an = __shfl_sync(0xffffffffu, iA, s + 1);
            int bn = __shfl_sync(0xffffffffu, iB, s + 1);
            if (lane == 0) {
                int st = (s + 1) & 1;
                void* mb = &mbar[st];
                mbar_expect_tx(mb, 2 * MAT_BYTES);
                bulk_cp(st ? bufA1 : bufA0, tab + (size_t)an * D, MAT_BYTES, mb);
                bulk_cp(st ? bufB1 : bufB0, tab + (size_t)bn * D, MAT_BYTES, mb);
            }
        }
        if (s & 1) { mbar_wait(&mbar[1], ph1); ph1 ^= 1u; }
        else       { mbar_wait(&mbar[0], ph0); ph0 ^= 1u; }
        const float4* wp = (s & 1) ? (h ? bufB1 : bufA1) : (h ? bufB0 : bufA0);
        mm_step2(c0, c1, wp);
    }

    // ---- Q_t = P_A * P_B (warp-local; h=0 lanes end with Q rows) ----
    if (h == 1 && act) store2((float*)bufB0, r0, r1, c0, c1);
    __syncwarp();
    mm_step2(c0, c1, bufB0);

    // publish Q_t and fan-in
    if (h == 0 && act)
        store2(g_q + (size_t)(b * NT + t) * D, r0, r1, c0, c1);
    __threadfence();                       // release: Q visible gpu-wide
    __syncwarp();

    int old = 0;
    if (lane == 0) old = atomicAdd(&g_cnt[b], 1);
    old = __shfl_sync(0xffffffffu, old, 0);
    if (old != NT - 1) return;             // not last: done

    // ---- last finisher: out = Q0 * Q1 * Q2 ----
    __threadfence();                       // acquire side
    if (lane == 0) {
        mbar_expect_tx(&mbar[0], 2 * MAT_BYTES);
        bulk_cp(bufA0, g_q + (size_t)(b * NT + 1) * D, MAT_BYTES, &mbar[0]);
        bulk_cp(bufA1, g_q + (size_t)(b * NT + 2) * D, MAT_BYTES, &mbar[0]);
    }
    // load Q0 rows (both halves load the same rows -> redundant but uniform)
    {
        const float4* q0 = (const float4*)(g_q + (size_t)(b * NT + 0) * D);
        #pragma unroll
        for (int q = 0; q < 7; ++q) {
            float4 v0 = q0[r0 * 7 + q];
            float4 v1 = q0[r1 * 7 + q];
            c0[4*q] = v0.x; c0[4*q+1] = v0.y; c0[4*q+2] = v0.z; c0[4*q+3] = v0.w;
            c1[4*q] = v1.x; c1[4*q+1] = v1.y; c1[4*q+2] = v1.z; c1[4*q+3] = v1.w;
        }
    }
    mbar_wait(&mbar[0], ph0);
    mm_step2(c0, c1, bufA0);               // * Q1
    mm_step2(c0, c1, bufA1);               // * Q2
    if (h == 0 && act)
        store2(out + (size_t)b * D, r0, r1, c0, c1);
}

extern "C" void kernel_launch(void* const* d_in, const int* in_sizes, int n_in,
                              void* d_out, int out_size)
{
    const int*   sent;
    const float* tab;
    if (in_sizes[0] < in_sizes[1]) {
        sent = (const int*)d_in[0];
        tab  = (const float*)d_in[1];
    } else {
        sent = (const int*)d_in[1];
        tab  = (const float*)d_in[0];
    }
    int B = out_size / D;   // 512

    w2m_zero<<<1, NB>>>();                               // reset fan-in counters
    w2m_main<<<B * NT, 32>>>(sent, tab, (float*)d_out);  // 1536 one-warp blocks
}